// round 14
// baseline (speedup 1.0000x reference)
#include <cuda_runtime.h>
#include <cstdint>

namespace {

constexpr int Tn = 512;
constexpr int Pn = 64;
constexpr int NB = 8;       // batch rows per CTA (= MMA N)
constexpr int NT = 512;     // 16 warps, one m16 tile each
constexpr int KS = 14;      // k16 steps (K=224: 72 hi*hi | 72 lo*hi | 72 hi*lo | 8 pad)
constexpr int BKS = 132;    // B row stride in u32 words (== 4 mod 32, 8B aligned)

__device__ __forceinline__ uint16_t f2bf(float x) {
    uint16_t r;
    asm("cvt.rn.bf16.f32 %0, %1;" : "=h"(r) : "f"(x));
    return r;
}
__device__ __forceinline__ float bf2f(uint16_t h) {
    return __uint_as_float((uint32_t)h << 16);
}
__device__ __forceinline__ float tanh_a(float x) {
    float y;
    asm("tanh.approx.f32 %0, %1;" : "=f"(y) : "f"(x));
    return y;
}
__device__ __forceinline__ float sig_a(float x) {
    return fmaf(tanh_a(0.5f * x), 0.5f, 0.5f);
}

__device__ __forceinline__ void mma16816(float d[4], const uint32_t a[4],
                                         const uint32_t b[2]) {
    asm volatile(
        "mma.sync.aligned.m16n8k16.row.col.f32.bf16.bf16.f32 "
        "{%0,%1,%2,%3}, {%4,%5,%6,%7}, {%8,%9}, {%0,%1,%2,%3};"
        : "+f"(d[0]), "+f"(d[1]), "+f"(d[2]), "+f"(d[3])
        : "r"(a[0]), "r"(a[1]), "r"(a[2]), "r"(a[3]), "r"(b[0]), "r"(b[1]));
}

// permuted A row m -> original gate row j = gate*64 + unit
// gate = m&3, unit = 4*(m>>4) + ((m>>2)&3)
__device__ __forceinline__ int jrow(int m) {
    return (m & 3) * 64 + 4 * (m >> 4) + ((m >> 2) & 3);
}

// B u16 slot for logical K index k, under k-pair interleave
// (per 8-word group, word order [0,4,1,5,2,6,3,7] so frag pairs are adjacent)
__device__ __forceinline__ int bslot(int k) {
    const int grp = k >> 4, k2 = (k >> 1) & 7, half = k & 1;
    const int word = 8 * grp + 2 * (k2 & 3) + (k2 >> 2);
    return 2 * word + half;
}

__device__ __forceinline__ uint16_t elemA(
    const float* __restrict__ Whh, const float* __restrict__ Wih, int j, int c)
{
    if (c >= 216) return (uint16_t)0;
    const int kk = c % 72;
    const float w = (kk < 64) ? __ldg(Whh + j * 64 + kk)
                              : __ldg(Wih + j * 8 + (kk - 64));
    const uint16_t h = f2bf(w);
    if (c >= 72 && c < 144) return f2bf(w - bf2f(h));
    return h;
}
__device__ __forceinline__ uint32_t packA(
    const float* __restrict__ Whh, const float* __restrict__ Wih, int j, int c)
{
    return (uint32_t)elemA(Whh, Wih, j, c) |
           ((uint32_t)elemA(Whh, Wih, j, c + 1) << 16);
}

// One m16 tile per warp: rows 16*wrp + {g, g+8}
__device__ void loadA(uint32_t Af[KS][4],
                      const float* __restrict__ Whh, const float* __restrict__ Wih,
                      int wrp, int g, int tg)
{
    const int r0 = 16 * wrp + g;
#pragma unroll
    for (int ks = 0; ks < KS; ks++) {
        const int c0 = 16 * ks + 2 * tg;
        Af[ks][0] = packA(Whh, Wih, jrow(r0),     c0);
        Af[ks][1] = packA(Whh, Wih, jrow(r0 + 8), c0);
        Af[ks][2] = packA(Whh, Wih, jrow(r0),     c0 + 8);
        Af[ks][3] = packA(Whh, Wih, jrow(r0 + 8), c0 + 8);
    }
}

using u64 = unsigned long long;

// GEMM step: 14 LDS.64 B frags, 14 HMMA, store D to warp's sact region
// sw layout [gate][uloc 0..3][n] gate stride 72 (2-way ST.64, CF act LDS)
__device__ __forceinline__ void gemm_step(
    const uint32_t Af[KS][4], const uint32_t* __restrict__ Bp,
    float* __restrict__ sw, int g, int tg)
{
    uint32_t bf[KS][2];
    const u64* brow = (const u64*)Bp + g * (BKS / 2);
#pragma unroll
    for (int ks = 0; ks < KS; ks++) {
        u64 v = brow[4 * ks + tg];          // words 8ks+2tg, +1 = frag pair
        bf[ks][0] = (uint32_t)v;
        bf[ks][1] = (uint32_t)(v >> 32);
    }
    float acc[2][4] = {};
#pragma unroll
    for (int ks = 0; ks < KS; ks++) mma16816(acc[ks & 1], Af[ks], bf[ks]);

    const int gate = g & 3;
    const int u0   = g >> 2;
    *(float2*)&sw[gate * 72 + u0 * 8 + 2 * tg] =
        make_float2(acc[0][0] + acc[1][0], acc[0][1] + acc[1][1]);
    *(float2*)&sw[gate * 72 + (u0 + 2) * 8 + 2 * tg] =
        make_float2(acc[0][2] + acc[1][2], acc[0][3] + acc[1][3]);
}

// Activation: lane owns (unit gu, batch n); h -> Bnext (split bf16) + opt shf.
__device__ __forceinline__ void act_one(
    const float* __restrict__ sw, uint32_t* __restrict__ Bnext,
    float* __restrict__ shf, const float* bi4,
    int n, int uloc, int gu, float& c, bool dec)
{
    const float gi = sw[0 * 72 + uloc * 8 + n] + bi4[0];
    const float gf = sw[1 * 72 + uloc * 8 + n] + bi4[1];
    const float gg = sw[2 * 72 + uloc * 8 + n] + bi4[2];
    const float go = sw[3 * 72 + uloc * 8 + n] + bi4[3];
    c = sig_a(gf) * c + sig_a(gi) * tanh_a(gg);
    const float h = sig_a(go) * tanh_a(c);
    const uint16_t hh = f2bf(h);
    const uint16_t hl = f2bf(h - bf2f(hh));
    uint16_t* row = (uint16_t*)(Bnext + n * BKS);
    row[bslot(gu)]       = hh;
    row[bslot(72 + gu)]  = hh;
    row[bslot(144 + gu)] = hl;
    if (dec) shf[n * 68 + gu] = h;
}

__device__ __forceinline__ void store_x(uint32_t* __restrict__ Bp, int n, int f,
                                        float x)
{
    const uint16_t h  = f2bf(x);
    const uint16_t lo = f2bf(x - bf2f(h));
    uint16_t* row = (uint16_t*)(Bp + n * BKS);
    row[bslot(64 + f)]  = h;
    row[bslot(136 + f)] = h;
    row[bslot(208 + f)] = lo;
}

__global__ void __launch_bounds__(NT, 1)
seq2seq_lstm_mma(
    const float* __restrict__ input,
    const float* __restrict__ eWih, const float* __restrict__ eWhh,
    const float* __restrict__ ebih, const float* __restrict__ ebhh,
    const float* __restrict__ dWih, const float* __restrict__ dWhh,
    const float* __restrict__ dbih, const float* __restrict__ dbhh,
    const float* __restrict__ fcW,  const float* __restrict__ fcb,
    float* __restrict__ out)
{
    __shared__ uint32_t Bp[2][NB * BKS];   // double-buffered B [parity][n][word]
    __shared__ float sact[16 * 288];       // per-warp D regions
    __shared__ float shf[NB * 68];         // fp32 h for decoder fc
    __shared__ float sfcw[8 * 64];
    __shared__ float sfcb[8];

    const int tid  = threadIdx.x;
    const int lane = tid & 31;
    const int wrp  = tid >> 5;
    const int g    = lane >> 2;
    const int tg   = lane & 3;
    const int b0   = blockIdx.x * NB;

    float* sw = sact + wrp * 288;

    // activation role: one (unit, n) per lane
    const int an  = lane & 7;
    const int ul  = lane >> 3;             // uloc 0..3
    const int gu  = 4 * wrp + ul;          // global unit

    sfcw[tid] = fcW[tid];                  // 512 == 8*64 exactly
    if (tid < 8) sfcb[tid] = fcb[tid];
    for (int i = tid; i < 2 * NB * BKS; i += NT) ((uint32_t*)Bp)[i] = 0;

    uint32_t Af[KS][4];
    loadA(Af, eWhh, eWih, wrp, g, tg);

    float bi[4];
#pragma unroll
    for (int gt = 0; gt < 4; gt++)
        bi[gt] = ebih[gt * 64 + gu] + ebhh[gt * 64 + gu];

    const bool xth = tid < NB * 8;
    const int  xn  = tid >> 3, xf = tid & 7;
    const float* xptr = input + ((size_t)(b0 + xn) * Tn) * 8 + xf;
    float xreg = 0.0f, xlast = 0.0f;
    if (xth) {
        xlast = __ldg(xptr);
        store_x(Bp[0], xn, xf, xlast);       // x(0)
        xreg = __ldg(xptr + 8);              // x(1)
    }
    __syncthreads();

    float c = 0.0f;

    // ================= encoder: 1 CTA barrier / step =================
    for (int t = 0; t < Tn; t++) {
        gemm_step(Af, Bp[t & 1], sw, g, tg);
        float xpre = (xth && t + 2 < Tn) ? __ldg(xptr + (size_t)(t + 2) * 8) : 0.0f;
        __syncwarp();

        uint32_t* Bn = Bp[(t + 1) & 1];
        act_one(sw, Bn, shf, bi, an, ul, gu, c, false);
        if (xth) {
            const float xs = (t + 1 < Tn) ? xreg : xlast;   // replay x_last at end
            store_x(Bn, xn, xf, xs);
            xlast = xs;
            xreg  = xpre;
        }
        __syncthreads();
    }
    // B[0] holds h_enc(final) + x(T-1)

    // ---- decoder weights ----
    loadA(Af, dWhh, dWih, wrp, g, tg);
#pragma unroll
    for (int gt = 0; gt < 4; gt++)
        bi[gt] = dbih[gt * 64 + gu] + dbhh[gt * 64 + gu];

    // ================= decoder =================
    for (int p = 0; p < Pn; p++) {
        const int pr = p & 1;
        gemm_step(Af, Bp[pr], sw, g, tg);
        __syncwarp();

        uint32_t* Bn = Bp[pr ^ 1];
        act_one(sw, Bn, shf, bi, an, ul, gu, c, true);
        __syncthreads();   // h (B + shf) ready

        if (xth) {         // pred = h @ fcW^T + fcb ; also next x
            float a = sfcb[xf];
            const float4* hr = (const float4*)&shf[xn * 68];
            const float4* wr = (const float4*)&sfcw[xf * 64];
#pragma unroll
            for (int k = 0; k < 16; k++) {
                float4 hv = hr[k], wv = wr[k];
                a = fmaf(hv.x, wv.x, a);
                a = fmaf(hv.y, wv.y, a);
                a = fmaf(hv.z, wv.z, a);
                a = fmaf(hv.w, wv.w, a);
            }
            out[((size_t)(b0 + xn) * Pn + p) * 8 + xf] = a;
            store_x(Bn, xn, xf, a);
        }
        __syncthreads();   // x ready for next step
    }
}

} // anonymous namespace

extern "C" void kernel_launch(void* const* d_in, const int* in_sizes, int n_in,
                              void* d_out, int out_size)
{
    const float* input = (const float*)d_in[0];
    const float* eWih  = (const float*)d_in[1];
    const float* eWhh  = (const float*)d_in[2];
    const float* ebih  = (const float*)d_in[3];
    const float* ebhh  = (const float*)d_in[4];
    const float* dWih  = (const float*)d_in[5];
    const float* dWhh  = (const float*)d_in[6];
    const float* dbih  = (const float*)d_in[7];
    const float* dbhh  = (const float*)d_in[8];
    const float* fcW   = (const float*)d_in[9];
    const float* fcb   = (const float*)d_in[10];
    float* out = (float*)d_out;

    seq2seq_lstm_mma<<<1024 / NB, NT>>>(input, eWih, eWhh, ebih, ebhh,
                                        dWih, dWhh, dbih, dbhh, fcW, fcb, out);
}

// round 15
// speedup vs baseline: 1.5895x; 1.5895x over previous
#include <cuda_runtime.h>
#include <cstdint>

namespace {

constexpr int Tn = 512;
constexpr int Pn = 64;
constexpr int NB = 8;       // batch rows per CTA (= MMA N)
constexpr int NT = 256;     // 8 warps, two m16 tiles each
constexpr int KS = 14;      // k16 steps (K=224: 72 hi*hi | 72 lo*hi | 72 hi*lo | 8 pad)
constexpr int BKS = 136;    // B row stride in u32 words (== 8 mod 32, u64 aligned)

using u64 = unsigned long long;

__device__ __forceinline__ uint16_t f2bf(float x) {
    uint16_t r;
    asm("cvt.rn.bf16.f32 %0, %1;" : "=h"(r) : "f"(x));
    return r;
}
__device__ __forceinline__ float bf2f(uint16_t h) {
    return __uint_as_float((uint32_t)h << 16);
}
__device__ __forceinline__ float tanh_a(float x) {
    float y;
    asm("tanh.approx.f32 %0, %1;" : "=f"(y) : "f"(x));
    return y;
}
__device__ __forceinline__ float sig_a(float x) {
    return fmaf(tanh_a(0.5f * x), 0.5f, 0.5f);
}

__device__ __forceinline__ void mma16816(float d[4], const uint32_t a[4],
                                         const uint32_t b[2]) {
    asm volatile(
        "mma.sync.aligned.m16n8k16.row.col.f32.bf16.bf16.f32 "
        "{%0,%1,%2,%3}, {%4,%5,%6,%7}, {%8,%9}, {%0,%1,%2,%3};"
        : "+f"(d[0]), "+f"(d[1]), "+f"(d[2]), "+f"(d[3])
        : "r"(a[0]), "r"(a[1]), "r"(a[2]), "r"(a[3]), "r"(b[0]), "r"(b[1]));
}

// permuted A row m -> original gate row: gate=(m>>3)&3, unit=8*(m>>5)+(m&7)
__device__ __forceinline__ int jrow(int m) {
    return ((m >> 3) & 3) * 64 + 8 * (m >> 5) + (m & 7);
}

// B u16 slot for logical K index k (k-pair interleave: per 8-word group,
// word order [0,4,1,5,2,6,3,7] so a thread's two B-frag words are adjacent)
__device__ __forceinline__ int bslot(int k) {
    const int grp = k >> 4, k2 = (k >> 1) & 7, half = k & 1;
    const int word = 8 * grp + 2 * (k2 & 3) + (k2 >> 2);
    return 2 * word + half;
}

__device__ __forceinline__ uint16_t elemA(
    const float* __restrict__ Whh, const float* __restrict__ Wih, int j, int c)
{
    if (c >= 216) return (uint16_t)0;
    const int kk = c % 72;
    const float w = (kk < 64) ? __ldg(Whh + j * 64 + kk)
                              : __ldg(Wih + j * 8 + (kk - 64));
    const uint16_t h = f2bf(w);
    if (c >= 72 && c < 144) return f2bf(w - bf2f(h));
    return h;
}
__device__ __forceinline__ uint32_t packA(
    const float* __restrict__ Whh, const float* __restrict__ Wih, int j, int c)
{
    return (uint32_t)elemA(Whh, Wih, j, c) |
           ((uint32_t)elemA(Whh, Wih, j, c + 1) << 16);
}

__device__ void loadA(uint32_t Af[2][KS][4],
                      const float* __restrict__ Whh, const float* __restrict__ Wih,
                      int wrp, int g, int tg)
{
#pragma unroll
    for (int tile = 0; tile < 2; tile++) {
        const int r0 = 16 * (2 * wrp + tile) + g;
#pragma unroll
        for (int ks = 0; ks < KS; ks++) {
            const int c0 = 16 * ks + 2 * tg;
            Af[tile][ks][0] = packA(Whh, Wih, jrow(r0),     c0);
            Af[tile][ks][1] = packA(Whh, Wih, jrow(r0 + 8), c0);
            Af[tile][ks][2] = packA(Whh, Wih, jrow(r0),     c0 + 8);
            Af[tile][ks][3] = packA(Whh, Wih, jrow(r0 + 8), c0 + 8);
        }
    }
}

// GEMM: 14 LDS.64 B frags, 28 HMMA (4 ILP chains), results stay in registers.
// d[0] = {i_n0,i_n1,f_n0,f_n1}, d[1] = {g_n0,g_n1,o_n0,o_n1} for unit 8w+G.
__device__ __forceinline__ void gemm_step(
    const uint32_t Af[2][KS][4], const uint32_t* __restrict__ Bp,
    float d[2][4], int g, int tg)
{
    uint32_t bf[KS][2];
    const u64* brow = (const u64*)Bp + g * (BKS / 2);
#pragma unroll
    for (int ks = 0; ks < KS; ks++) {
        u64 v = brow[4 * ks + tg];
        bf[ks][0] = (uint32_t)v;
        bf[ks][1] = (uint32_t)(v >> 32);
    }
    float acc[2][2][4] = {};
#pragma unroll
    for (int ks = 0; ks < KS; ks++) {
        mma16816(acc[0][ks & 1], Af[0][ks], bf[ks]);
        mma16816(acc[1][ks & 1], Af[1][ks], bf[ks]);
    }
#pragma unroll
    for (int tile = 0; tile < 2; tile++)
#pragma unroll
        for (int j = 0; j < 4; j++)
            d[tile][j] = acc[tile][0][j] + acc[tile][1][j];
}

// split-bf16 store of h(u, n) into Bnext
__device__ __forceinline__ void store_h(uint32_t* __restrict__ Bnext,
                                        int n, int u, float h)
{
    const uint16_t hh = f2bf(h);
    const uint16_t hl = f2bf(h - bf2f(hh));
    uint16_t* row = (uint16_t*)(Bnext + n * BKS);
    row[bslot(u)]       = hh;
    row[bslot(72 + u)]  = hh;
    row[bslot(144 + u)] = hl;
}

__device__ __forceinline__ void store_x(uint32_t* __restrict__ Bp, int n, int f,
                                        float x)
{
    const uint16_t h  = f2bf(x);
    const uint16_t lo = f2bf(x - bf2f(h));
    uint16_t* row = (uint16_t*)(Bp + n * BKS);
    row[bslot(64 + f)]  = h;
    row[bslot(136 + f)] = h;
    row[bslot(208 + f)] = lo;
}

__global__ void __launch_bounds__(NT, 1)
seq2seq_lstm_mma(
    const float* __restrict__ input,
    const float* __restrict__ eWih, const float* __restrict__ eWhh,
    const float* __restrict__ ebih, const float* __restrict__ ebhh,
    const float* __restrict__ dWih, const float* __restrict__ dWhh,
    const float* __restrict__ dbih, const float* __restrict__ dbhh,
    const float* __restrict__ fcW,  const float* __restrict__ fcb,
    float* __restrict__ out)
{
    __shared__ uint32_t Bp[2][NB * BKS];   // double-buffered B [parity][n][word]
    __shared__ float shf[NB * 68];         // fp32 h for decoder fc
    __shared__ float sfcw[8 * 64];
    __shared__ float sfcb[8];

    const int tid  = threadIdx.x;
    const int lane = tid & 31;
    const int wrp  = tid >> 5;
    const int g    = lane >> 2;            // G: D rows / B column group
    const int tg   = lane & 3;             // T
    const int b0   = blockIdx.x * NB;

    const int u  = 8 * wrp + g;            // unit owned by this thread
    const int n0 = 2 * tg, n1 = n0 + 1;    // batch rows owned

    sfcw[tid]      = fcW[tid];
    sfcw[tid + NT] = fcW[tid + NT];
    if (tid < 8) sfcb[tid] = fcb[tid];
    for (int i = tid; i < 2 * NB * BKS; i += NT) ((uint32_t*)Bp)[i] = 0;

    uint32_t Af[2][KS][4];
    loadA(Af, eWhh, eWih, wrp, g, tg);

    float bi[4];
#pragma unroll
    for (int gt = 0; gt < 4; gt++)
        bi[gt] = ebih[gt * 64 + u] + ebhh[gt * 64 + u];

    const bool xth = tid < NB * 8;
    const int  xn  = tid >> 3, xf = tid & 7;
    const float* xptr = input + ((size_t)(b0 + xn) * Tn) * 8 + xf;
    float xreg = 0.0f, xlast = 0.0f;
    if (xth) {
        xlast = __ldg(xptr);
        store_x(Bp[0], xn, xf, xlast);       // x(0)
        xreg = __ldg(xptr + 8);              // x(1)
    }
    __syncthreads();

    float c0 = 0.0f, c1 = 0.0f;

    // ============ encoder: 1 barrier / step, reg-local activation ============
    for (int t = 0; t < Tn; t++) {
        float d[2][4];
        gemm_step(Af, Bp[t & 1], d, g, tg);
        float xpre = (xth && t + 2 < Tn) ? __ldg(xptr + (size_t)(t + 2) * 8) : 0.0f;

        uint32_t* Bn = Bp[(t + 1) & 1];
        // gates straight from accumulators
        c0 = sig_a(d[0][2] + bi[1]) * c0 + sig_a(d[0][0] + bi[0]) * tanh_a(d[1][0] + bi[2]);
        c1 = sig_a(d[0][3] + bi[1]) * c1 + sig_a(d[0][1] + bi[0]) * tanh_a(d[1][1] + bi[2]);
        store_h(Bn, n0, u, sig_a(d[1][2] + bi[3]) * tanh_a(c0));
        store_h(Bn, n1, u, sig_a(d[1][3] + bi[3]) * tanh_a(c1));

        if (xth) {
            const float xs = (t + 1 < Tn) ? xreg : xlast;   // replay x_last at end
            store_x(Bn, xn, xf, xs);
            xlast = xs;
            xreg  = xpre;
        }
        __syncthreads();
    }
    // B[0] holds h_enc(final) + x(T-1)

    // ---- decoder weights ----
    loadA(Af, dWhh, dWih, wrp, g, tg);
#pragma unroll
    for (int gt = 0; gt < 4; gt++)
        bi[gt] = dbih[gt * 64 + u] + dbhh[gt * 64 + u];

    // ============ decoder ============
    for (int p = 0; p < Pn; p++) {
        const int pr = p & 1;
        float d[2][4];
        gemm_step(Af, Bp[pr], d, g, tg);

        uint32_t* Bn = Bp[pr ^ 1];
        c0 = sig_a(d[0][2] + bi[1]) * c0 + sig_a(d[0][0] + bi[0]) * tanh_a(d[1][0] + bi[2]);
        c1 = sig_a(d[0][3] + bi[1]) * c1 + sig_a(d[0][1] + bi[0]) * tanh_a(d[1][1] + bi[2]);
        const float h0 = sig_a(d[1][2] + bi[3]) * tanh_a(c0);
        const float h1 = sig_a(d[1][3] + bi[3]) * tanh_a(c1);
        store_h(Bn, n0, u, h0);
        store_h(Bn, n1, u, h1);
        shf[n0 * 68 + u] = h0;
        shf[n1 * 68 + u] = h1;
        __syncthreads();   // h (B + shf) ready

        if (xth) {         // pred = h @ fcW^T + fcb ; also next x
            float a = sfcb[xf];
            const float4* hr = (const float4*)&shf[xn * 68];
            const float4* wr = (const float4*)&sfcw[xf * 64];
#pragma unroll
            for (int k = 0; k < 16; k++) {
                float4 hv = hr[k], wv = wr[k];
                a = fmaf(hv.x, wv.x, a);
                a = fmaf(hv.y, wv.y, a);
                a = fmaf(hv.z, wv.z, a);
                a = fmaf(hv.w, wv.w, a);
            }
            out[((size_t)(b0 + xn) * Pn + p) * 8 + xf] = a;
            store_x(Bn, xn, xf, a);
        }
        __syncthreads();   // x ready for next step
    }
}

} // anonymous namespace

extern "C" void kernel_launch(void* const* d_in, const int* in_sizes, int n_in,
                              void* d_out, int out_size)
{
    const float* input = (const float*)d_in[0];
    const float* eWih  = (const float*)d_in[1];
    const float* eWhh  = (const float*)d_in[2];
    const float* ebih  = (const float*)d_in[3];
    const float* ebhh  = (const float*)d_in[4];
    const float* dWih  = (const float*)d_in[5];
    const float* dWhh  = (const float*)d_in[6];
    const float* dbih  = (const float*)d_in[7];
    const float* dbhh  = (const float*)d_in[8];
    const float* fcW   = (const float*)d_in[9];
    const float* fcb   = (const float*)d_in[10];
    float* out = (float*)d_out;

    seq2seq_lstm_mma<<<1024 / NB, NT>>>(input, eWih, eWhh, ebih, ebhh,
                                        dWih, dWhh, dbih, dbhh, fcW, fcb, out);
}